// round 9
// baseline (speedup 1.0000x reference)
#include <cuda_runtime.h>
#include <cstdint>

// Round-8 winner + memory-instruction compaction:
//  - consecutive-pair layout (elements 2i, 2i+1): output block at byte 24i is
//    8B-aligned -> stores become 3x st.global.cs.v2.f32 (was 6 scalar)
//  - both input float4s fetched by ONE 256-bit ld.global.nc.v8.b32 with the
//    evict_last L2 policy (32B aligned, warp-dense = 8 lines = data minimum)
//  - memory instructions per thread: 8 -> 4
//
// Closed form (Heisenberg picture), Cj=cos(x_j*pi + w0_j), Sj=sin(...):
//   z0 = K1*C0 + K2*S0*S1
//   z1 = K3*C1 + K4*C0*S1*S2 + K5*S0*S2
//   z2 = K6*C0*C2 + K7*C1*S2 + K8*C0*S1 + K9*S0*S1*C2 + K10*S0

__device__ __forceinline__ void ldg_pair(const float4* p, uint64_t pol,
                                         float4& a, float4& b) {
    asm("ld.global.nc.L2::cache_hint.v8.f32 {%0,%1,%2,%3,%4,%5,%6,%7}, [%8], %9;"
        : "=f"(a.x), "=f"(a.y), "=f"(a.z), "=f"(a.w),
          "=f"(b.x), "=f"(b.y), "=f"(b.z), "=f"(b.w)
        : "l"(p), "l"(pol));
}
__device__ __forceinline__ void stg_cs2(float* p, float v0, float v1) {
    asm volatile("st.global.cs.v2.f32 [%0], {%1, %2};" :: "l"(p), "f"(v0), "f"(v1));
}

__global__ void __launch_bounds__(256)
qfl_kernel(const float4* __restrict__ x, float* __restrict__ out,
           const float* __restrict__ w, int T /* = B/2 */) {
    __shared__ float K[13];
    if (threadIdx.x == 0) {
        float A = w[3], B = w[4], C = w[5];
        float sA, cA, sB, cB, sC, cC;
        sincosf(A, &sA, &cA);
        sincosf(B, &sB, &cB);
        sincosf(C, &sC, &cC);
        K[0] = w[0]; K[1] = w[1]; K[2] = w[2];
        K[3]  =  cA;
        K[4]  = -sA;
        K[5]  =  cA * cB;
        K[6]  = -cA * sB;
        K[7]  =  sA * sB;
        K[8]  =  cA * cB * cC;
        K[9]  = -cA * cB * sC;
        K[10] =  cA * sB * sC;
        K[11] = -sA * cB * cC;
        K[12] = -sA * sB * sC;
    }
    __syncthreads();

    const float w00 = K[0], w01 = K[1], w02 = K[2];
    const float K1 = K[3], K2 = K[4];
    const float K3 = K[5], K4 = K[6], K5 = K[7];
    const float K6 = K[8], K7 = K[9], K8 = K[10], K9 = K[11], K10 = K[12];

    int i = blockIdx.x * 256 + threadIdx.x;
    if (i >= T) return;

    // Evict-last L2 policy for the (L2-resident across replays) input.
    uint64_t pol;
    asm("createpolicy.fractional.L2::evict_last.b64 %0, 1.0;" : "=l"(pol));

    // One 256-bit load: elements 2i and 2i+1 (32B-aligned, warp-dense).
    float4 xa, xb;
    ldg_pair(&x[2 * i], pol, xa, xb);

    // Reference uses the literal 3.14159 — match it.
    const float PI_ = 3.14159f;

    float S0a, C0a, S1a, C1a, S2a, C2a;
    float S0b, C0b, S1b, C1b, S2b, C2b;
    __sincosf(fmaf(xa.x, PI_, w00), &S0a, &C0a);
    __sincosf(fmaf(xa.y, PI_, w01), &S1a, &C1a);
    __sincosf(fmaf(xa.z, PI_, w02), &S2a, &C2a);
    __sincosf(fmaf(xb.x, PI_, w00), &S0b, &C0b);
    __sincosf(fmaf(xb.y, PI_, w01), &S1b, &C1b);
    __sincosf(fmaf(xb.z, PI_, w02), &S2b, &C2b);

    // Element a
    float s01a = S0a * S1a;
    float az0 = fmaf(K1, C0a, K2 * s01a);
    float az1 = fmaf(K3, C1a, fmaf(K4, C0a * (S1a * S2a), K5 * (S0a * S2a)));
    float az2 = fmaf(K6, C0a * C2a,
                fmaf(K7, C1a * S2a,
                fmaf(K8, C0a * S1a,
                fmaf(K9, s01a * C2a, K10 * S0a))));

    // Element b
    float s01b = S0b * S1b;
    float bz0 = fmaf(K1, C0b, K2 * s01b);
    float bz1 = fmaf(K3, C1b, fmaf(K4, C0b * (S1b * S2b), K5 * (S0b * S2b)));
    float bz2 = fmaf(K6, C0b * C2b,
                fmaf(K7, C1b * S2b,
                fmaf(K8, C0b * S1b,
                fmaf(K9, s01b * C2b, K10 * S0b))));

    // 6 contiguous floats at byte offset 24*i (8B-aligned): 3x STG.64.cs.
    float* o = out + 6 * i;
    stg_cs2(o + 0, az0, az1);
    stg_cs2(o + 2, az2, bz0);
    stg_cs2(o + 4, bz1, bz2);
}

extern "C" void kernel_launch(void* const* d_in, const int* in_sizes, int n_in,
                              void* d_out, int out_size) {
    const float* x = (const float*)d_in[0];   // (B, 4) float32
    const float* w = (const float*)d_in[1];   // (2, 3) float32
    float* out = (float*)d_out;               // (B, 3) float32
    int B = in_sizes[0] / 4;
    int T = B / 2;                            // elements 2i, 2i+1 per thread

    qfl_kernel<<<(T + 255) / 256, 256>>>((const float4*)x, out, w, T);
}

// round 10
// speedup vs baseline: 1.1940x; 1.1940x over previous
#include <cuda_runtime.h>
#include <cstdint>

// Round-8 winner with ONE change: stores are plain write-back (no .cs).
// Rationale: the 56MB working set fits in the 126MB L2. evict_last loads pin
// the input; evict-first (.cs) stores were forcing early DRAM writeback of
// output lines that the next graph replay overwrites anyway. Default
// write-back stores let dirty output lines live in L2 across replays.
//
// Kernel structure (from r8):
//  - split-half ILP=2 (elements i and i+T): every LDG.128 warp-dense
//  - x loaded via createpolicy(evict_last) + ld.global.nc.L2::cache_hint
//
// Closed form (Heisenberg picture), Cj=cos(x_j*pi + w0_j), Sj=sin(...):
//   z0 = K1*C0 + K2*S0*S1
//   z1 = K3*C1 + K4*C0*S1*S2 + K5*S0*S2
//   z2 = K6*C0*C2 + K7*C1*S2 + K8*C0*S1 + K9*S0*S1*C2 + K10*S0

__device__ __forceinline__ float4 ldg_el(const float4* p, uint64_t pol) {
    float4 v;
    asm("ld.global.nc.L2::cache_hint.v4.f32 {%0,%1,%2,%3}, [%4], %5;"
        : "=f"(v.x), "=f"(v.y), "=f"(v.z), "=f"(v.w) : "l"(p), "l"(pol));
    return v;
}

__global__ void __launch_bounds__(256)
qfl_kernel(const float4* __restrict__ x, float* __restrict__ out,
           const float* __restrict__ w, int T /* = B/2 */) {
    __shared__ float K[13];
    if (threadIdx.x == 0) {
        float A = w[3], B = w[4], C = w[5];
        float sA, cA, sB, cB, sC, cC;
        sincosf(A, &sA, &cA);
        sincosf(B, &sB, &cB);
        sincosf(C, &sC, &cC);
        K[0] = w[0]; K[1] = w[1]; K[2] = w[2];
        K[3]  =  cA;
        K[4]  = -sA;
        K[5]  =  cA * cB;
        K[6]  = -cA * sB;
        K[7]  =  sA * sB;
        K[8]  =  cA * cB * cC;
        K[9]  = -cA * cB * sC;
        K[10] =  cA * sB * sC;
        K[11] = -sA * cB * cC;
        K[12] = -sA * sB * sC;
    }
    __syncthreads();

    const float w00 = K[0], w01 = K[1], w02 = K[2];
    const float K1 = K[3], K2 = K[4];
    const float K3 = K[5], K4 = K[6], K5 = K[7];
    const float K6 = K[8], K7 = K[9], K8 = K[10], K9 = K[11], K10 = K[12];

    int i = blockIdx.x * 256 + threadIdx.x;
    if (i >= T) return;
    int j = i + T;

    // Evict-last L2 policy: input stays L2-resident across graph replays.
    uint64_t pol;
    asm("createpolicy.fractional.L2::evict_last.b64 %0, 1.0;" : "=l"(pol));

    // Warp-dense loads (consecutive lanes -> consecutive float4), MLP=2.
    const float4 xa = ldg_el(&x[i], pol);
    const float4 xb = ldg_el(&x[j], pol);

    // Reference uses the literal 3.14159 — match it.
    const float PI_ = 3.14159f;

    float S0a, C0a, S1a, C1a, S2a, C2a;
    float S0b, C0b, S1b, C1b, S2b, C2b;
    __sincosf(fmaf(xa.x, PI_, w00), &S0a, &C0a);
    __sincosf(fmaf(xa.y, PI_, w01), &S1a, &C1a);
    __sincosf(fmaf(xa.z, PI_, w02), &S2a, &C2a);
    __sincosf(fmaf(xb.x, PI_, w00), &S0b, &C0b);
    __sincosf(fmaf(xb.y, PI_, w01), &S1b, &C1b);
    __sincosf(fmaf(xb.z, PI_, w02), &S2b, &C2b);

    // Element a
    float s01a = S0a * S1a;
    float az0 = fmaf(K1, C0a, K2 * s01a);
    float az1 = fmaf(K3, C1a, fmaf(K4, C0a * (S1a * S2a), K5 * (S0a * S2a)));
    float az2 = fmaf(K6, C0a * C2a,
                fmaf(K7, C1a * S2a,
                fmaf(K8, C0a * S1a,
                fmaf(K9, s01a * C2a, K10 * S0a))));

    // Element b
    float s01b = S0b * S1b;
    float bz0 = fmaf(K1, C0b, K2 * s01b);
    float bz1 = fmaf(K3, C1b, fmaf(K4, C0b * (S1b * S2b), K5 * (S0b * S2b)));
    float bz2 = fmaf(K6, C0b * C2b,
                fmaf(K7, C1b * S2b,
                fmaf(K8, C0b * S1b,
                fmaf(K9, s01b * C2b, K10 * S0b))));

    // Plain write-back stores: dirty lines stay in L2 across replays.
    float* oa = out + 3 * i;
    oa[0] = az0;
    oa[1] = az1;
    oa[2] = az2;
    float* ob = out + 3 * j;
    ob[0] = bz0;
    ob[1] = bz1;
    ob[2] = bz2;
}

extern "C" void kernel_launch(void* const* d_in, const int* in_sizes, int n_in,
                              void* d_out, int out_size) {
    const float* x = (const float*)d_in[0];   // (B, 4) float32
    const float* w = (const float*)d_in[1];   // (2, 3) float32
    float* out = (float*)d_out;               // (B, 3) float32
    int B = in_sizes[0] / 4;
    int T = B / 2;                            // elements i and i+T per thread

    qfl_kernel<<<(T + 255) / 256, 256>>>((const float4*)x, out, w, T);
}